// round 15
// baseline (speedup 1.0000x reference)
#include <cuda_runtime.h>
#include <cuda_bf16.h>
#include <cstdint>

#define BATCH 8
#define DIM   128
#define NTOK  32768
#define SPLIT 18               // 144 CTAs on 148 SMs
#define NST1  1024             // total 32-token stages per batch (k1)
#define NST3  512              // total 64-token stages per batch (k3)
#define EPS 1e-8f

typedef uint32_t u32;
typedef uint64_t u64;

// ---------------- scratch ----------------
__device__ __align__(16) float g_KVp[BATCH][SPLIT][DIM * DIM];
__device__ __align__(16) float g_Ksump[BATCH][SPLIT][DIM];
__device__ __align__(16) __nv_bfloat16 g_KVThi[BATCH][DIM * DIM]; // KV^T (row e, col d)
__device__ __align__(16) __nv_bfloat16 g_KVTlo[BATCH][DIM * DIM];
__device__ __align__(16) float g_Ksum[BATCH][DIM];

// ---------------- helpers ----------------
__device__ __forceinline__ u32 smem_u32(const void* p) {
    u32 a;
    asm("{ .reg .u64 t; cvta.to.shared.u64 t, %1; cvt.u32.u64 %0, t; }" : "=r"(a) : "l"(p));
    return a;
}
__device__ __forceinline__ void ldsm4(u32& r0, u32& r1, u32& r2, u32& r3, u32 addr) {
    asm volatile("ldmatrix.sync.aligned.m8n8.x4.shared.b16 {%0,%1,%2,%3}, [%4];"
                 : "=r"(r0), "=r"(r1), "=r"(r2), "=r"(r3) : "r"(addr));
}
// NON-volatile: lets ptxas interleave convert ALU work with the HMMA stream.
__device__ __forceinline__ void mma16816(float* c, u32 a0, u32 a1, u32 a2, u32 a3,
                                         u32 b0, u32 b1) {
    asm("mma.sync.aligned.m16n8k16.row.col.f32.bf16.bf16.f32 "
        "{%0,%1,%2,%3}, {%4,%5,%6,%7}, {%8,%9}, {%0,%1,%2,%3};"
        : "+f"(c[0]), "+f"(c[1]), "+f"(c[2]), "+f"(c[3])
        : "r"(a0), "r"(a1), "r"(a2), "r"(a3), "r"(b0), "r"(b1));
}
__device__ __forceinline__ void cpa16(u32 dst, const void* src) {
    asm volatile("cp.async.cg.shared.global [%0], [%1], 16;" :: "r"(dst), "l"(src));
}
#define CP_COMMIT() asm volatile("cp.async.commit_group;" ::: "memory")
#define CP_WAIT0()  asm volatile("cp.async.wait_group 0;" ::: "memory")
#define CP_WAIT1()  asm volatile("cp.async.wait_group 1;" ::: "memory")

__device__ __forceinline__ float phi(float x) { return x > 0.0f ? x + 1.0f : __expf(x); }

// truncation split: hi = top-16-bits of a,b packed; lo = bf16-rounded remainders
__device__ __forceinline__ void split2c(float a, float b, u32& hi, u32& lo) {
    u32 ab = __float_as_uint(a), bb = __float_as_uint(b);
    hi = __byte_perm(ab, bb, 0x7632);
    float la = a - __uint_as_float(ab & 0xffff0000u);
    float lb = b - __uint_as_float(bb & 0xffff0000u);
    asm("cvt.rn.bf16x2.f32 %0, %1, %2;" : "=r"(lo) : "f"(lb), "f"(la));
}

// ====================================================================
// k1: KV[d][e] = sum_n phi(K[d,n]) * V[e,n]     (UNCHANGED)
// 512 thr (16 warps), ~57 stages of 32 tokens, warp tile 32d x 32e.
// ====================================================================
#define P1 80
#define TB1 10240
#define STG1 40960
#define K1_RAW 81920
#define K1_KSB 147456
#define K1_SMEM 151552

__global__ __launch_bounds__(512, 1)
void k1_mma(const float* __restrict__ k, const float* __restrict__ v) {
    extern __shared__ __align__(16) char sm[];
    const u32 sb = smem_u32(sm);
    const int b = blockIdx.y, s = blockIdx.x;
    const int tid = threadIdx.x, wid = tid >> 5, lane = tid & 31;
    const int n4 = tid & 7, dr = tid >> 3;
    const int wd = wid >> 2, we = wid & 3;

    const int beg   = (s * NST1) / SPLIT;
    const int iters = ((s + 1) * NST1) / SPLIT - beg;

    const float* kb = k + (size_t)b * DIM * NTOK;
    const float* vb = v + (size_t)b * DIM * NTOK;

    const int rA = (lane & 7) + ((lane & 8) ? 8 : 0);
    const int cA = (lane & 16) ? 16 : 0;
    const int rB = (lane & 7) + ((lane & 16) ? 8 : 0);
    const int cB = (lane & 8) ? 16 : 0;

    float acc[2][4][4];
#pragma unroll
    for (int i = 0; i < 2; i++)
#pragma unroll
        for (int j = 0; j < 4; j++)
#pragma unroll
            for (int r = 0; r < 4; r++) acc[i][j][r] = 0.f;
    float ksum_l[2] = {0.f, 0.f};

    auto issue = [&](int tile) {
        if (tile >= iters) return;
        const int n0 = (beg + tile) * 32;
        const u32 rb = sb + K1_RAW + (tile & 1) * 32768;
#pragma unroll
        for (int c = 0; c < 2; c++) {
            const int ci = tid + c * 512;
            const int d = ci >> 3, col = ci & 7;
            cpa16(rb + d * 128 + col * 16, kb + (size_t)d * NTOK + n0 + col * 4);
            cpa16(rb + 16384 + d * 128 + col * 16, vb + (size_t)d * NTOK + n0 + col * 4);
        }
        CP_COMMIT();
    };

    auto convert_part = [&](int st, int part) {
        char* stp = sm + st * STG1;
        const char* rp = sm + K1_RAW + st * 32768;
        const int d = part * 64 + dr;
        const u32 roff = (u32)(d * 128 + n4 * 16);
        const u32 off  = (u32)(d * P1 + n4 * 8);
        float4 kx = *(const float4*)(rp + roff);
        float f0 = phi(kx.x), f1 = phi(kx.y), f2 = phi(kx.z), f3 = phi(kx.w);
        ksum_l[part] += (f0 + f1) + (f2 + f3);
        uint2 hi, lo;
        split2c(f0, f1, hi.x, lo.x);
        split2c(f2, f3, hi.y, lo.y);
        *(uint2*)(stp + 0       + off) = hi;
        *(uint2*)(stp + TB1     + off) = lo;
        float4 vx = *(const float4*)(rp + 16384 + roff);
        split2c(vx.x, vx.y, hi.x, lo.x);
        split2c(vx.z, vx.w, hi.y, lo.y);
        *(uint2*)(stp + 2 * TB1 + off) = hi;
        *(uint2*)(stp + 3 * TB1 + off) = lo;
    };

    issue(0); issue(1);
    CP_WAIT1();
    __syncthreads();
    convert_part(0, 0); convert_part(0, 1);

    for (int i = 0; i < iters; i++) {
        CP_WAIT0();
        __syncthreads();
        issue(i + 2);
        const u32 base = sb + (i & 1) * STG1;
        const bool cvt = (i + 1 < iters);
        const int stn = (i + 1) & 1;
#pragma unroll
        for (int kk = 0; kk < 2; kk++) {
            u32 bh[8], bl[8];
#pragma unroll
            for (int g = 0; g < 2; g++) {
                const u32 boff = (u32)((we * 32 + g * 16 + rB) * P1 + kk * 32 + cB);
                ldsm4(bh[g*4+0], bh[g*4+1], bh[g*4+2], bh[g*4+3], base + 2 * TB1 + boff);
                ldsm4(bl[g*4+0], bl[g*4+1], bl[g*4+2], bl[g*4+3], base + 3 * TB1 + boff);
            }
            u32 ah[2][4], al[2][4];
#pragma unroll
            for (int mt = 0; mt < 2; mt++) {
                const u32 aoff = (u32)((wd * 32 + mt * 16 + rA) * P1 + kk * 32 + cA);
                ldsm4(ah[mt][0], ah[mt][1], ah[mt][2], ah[mt][3], base + 0   + aoff);
                ldsm4(al[mt][0], al[mt][1], al[mt][2], al[mt][3], base + TB1 + aoff);
            }
            if (cvt) convert_part(stn, kk);
#pragma unroll
            for (int mt = 0; mt < 2; mt++)
#pragma unroll
                for (int nt = 0; nt < 4; nt++) {
                    float* c = acc[mt][nt];
                    const int bi = (nt >> 1) * 4 + (nt & 1) * 2;
                    mma16816(c, ah[mt][0], ah[mt][1], ah[mt][2], ah[mt][3], bh[bi], bh[bi+1]);
                    mma16816(c, ah[mt][0], ah[mt][1], ah[mt][2], ah[mt][3], bl[bi], bl[bi+1]);
                    mma16816(c, al[mt][0], al[mt][1], al[mt][2], al[mt][3], bh[bi], bh[bi+1]);
                }
        }
    }
    __syncthreads();
    float* kbuf = (float*)(sm + K1_KSB);
#pragma unroll
    for (int p = 0; p < 2; p++) kbuf[(p * 64 + dr) * 8 + n4] = ksum_l[p];
    __syncthreads();
    if (tid < 128) {
        float sum = 0.f;
#pragma unroll
        for (int i = 0; i < 8; i++) sum += kbuf[tid * 8 + i];
        g_Ksump[b][s][tid] = sum;
    }
    float* dst = &g_KVp[b][s][0];
    const int g = lane >> 2, tig = lane & 3;
#pragma unroll
    for (int mt = 0; mt < 2; mt++)
#pragma unroll
        for (int nt = 0; nt < 4; nt++) {
            const int d0 = wd * 32 + mt * 16 + g;
            const int e0 = we * 32 + nt * 8 + tig * 2;
            float* c = acc[mt][nt];
            *(float2*)(dst + d0 * DIM + e0)       = make_float2(c[0], c[1]);
            *(float2*)(dst + (d0 + 8) * DIM + e0) = make_float2(c[2], c[3]);
        }
}

// ====================================================================
// k2: reduce partials -> KV^T bf16 hi/lo + Ksum fp32   (UNCHANGED)
// ====================================================================
__global__ __launch_bounds__(256)
void k2_reduce() {
    const int idx = blockIdx.x * 256 + threadIdx.x;
    if (idx < BATCH * DIM * DIM) {
        const int b = idx >> 14, e = idx & 127, d = (idx >> 7) & 127;
        float sum = 0.f;
#pragma unroll
        for (int p = 0; p < SPLIT; p++) sum += g_KVp[b][p][d * DIM + e];
        __nv_bfloat16 h = __float2bfloat16(sum);
        g_KVThi[b][e * DIM + d] = h;
        g_KVTlo[b][e * DIM + d] = __float2bfloat16(sum - __bfloat162float(h));
    }
    if (idx < BATCH * DIM) {
        const int b = idx >> 7, d = idx & 127;
        float sum = 0.f;
#pragma unroll
        for (int p = 0; p < SPLIT; p++) sum += g_Ksump[b][p][d];
        g_Ksum[b][d] = sum;
    }
}

// ====================================================================
// k3: out^T[e][t] = z(t) * sum_d KV^T[e,d] * phi(Q[t,d])
// 512 thr (16 warps, 4/SMSP), ~29 stages of 64 tokens,
// warp tile 32e x 16t. cp.async staging; convert interleaved in MMA.
// ====================================================================
#define P3 272
#define K3_AHI 0
#define K3_ALO 34816
#define K3_QB  69632          // stage st: QHI +st*34816, QLO +17408
#define K3_RAW 139264         // + st*32768: [128 d][64 t] f32, pitch 256B
#define K3_ZS  204800         // 2 x 64 f32
#define K3_KS  205312         // 128 f32
#define K3_DEN 205824         // 2 x 8 x 64 f32 = 4096 B
#define K3_SMEM 209920

__global__ __launch_bounds__(512, 1)
void k3_mma(const float* __restrict__ q, float* __restrict__ out) {
    extern __shared__ __align__(16) char sm[];
    const u32 sb = smem_u32(sm);
    const int b = blockIdx.y, s = blockIdx.x;
    const int tid = threadIdx.x, wid = tid >> 5, lane = tid & 31;
    const int we = wid >> 2, wt = wid & 3;      // 32e x 16t warp tile
    const int grp = tid >> 6;                   // convert d-group (0..7), 8 pairs
    const int tl = tid & 63;                    // convert token (0..63)

    const int beg   = (s * NST3) / SPLIT;
    const int iters = ((s + 1) * NST3) / SPLIT - beg;

    // resident KV^T hi/lo
    for (int i = tid; i < DIM * 64; i += 512) {
        const int e = i >> 6, dp = i & 63;
        const u32 off = (u32)(e * P3 + dp * 4);
        *(u32*)(sm + K3_AHI + off) = *(const u32*)(&g_KVThi[b][e * DIM + dp * 2]);
        *(u32*)(sm + K3_ALO + off) = *(const u32*)(&g_KVTlo[b][e * DIM + dp * 2]);
    }
    float* zs = (float*)(sm + K3_ZS);
    float* ks = (float*)(sm + K3_KS);
    float* denp = (float*)(sm + K3_DEN);
    if (tid < 128) ks[tid] = g_Ksum[b][tid];

    const float* qb = q + (size_t)b * DIM * NTOK;
    float* ob = out + (size_t)b * DIM * NTOK;

    auto issue = [&](int tile) {
        if (tile >= iters) return;
        const int T0 = (beg + tile) * 64;
        const u32 rb = sb + K3_RAW + (tile & 1) * 32768;
#pragma unroll
        for (int c = 0; c < 4; c++) {
            const int ci = tid + c * 512;         // 0..2047
            const int d = ci >> 4, col = ci & 15;
            cpa16(rb + d * 256 + col * 16, qb + (size_t)d * NTOK + T0 + col * 4);
        }
        CP_COMMIT();
    };

    // convert 4 d-pairs (part p in {0,1}) of stage st; returns den partial
    auto convert3_part = [&](int st, int p) -> float {
        const char* rp = sm + K3_RAW + st * 32768;
        char* qsm = sm + K3_QB + st * 34816;
        uint4 hi4, lo4;
        u32* hp = (u32*)&hi4; u32* lp = (u32*)&lo4;
        float den_l = 0.f;
#pragma unroll
        for (int jj = 0; jj < 4; jj++) {
            const int dp = grp * 8 + p * 4 + jj, d0 = dp * 2;
            float f0 = phi(*(const float*)(rp + d0 * 256 + tl * 4));
            float f1 = phi(*(const float*)(rp + (d0 + 1) * 256 + tl * 4));
            split2c(f0, f1, hp[jj], lp[jj]);
            den_l += f0 * ks[d0] + f1 * ks[d0 + 1];
        }
        const u32 off = (u32)(tl * P3 + (grp * 8 + p * 4) * 4);
        *(uint4*)(qsm + off)         = hi4;
        *(uint4*)(qsm + 17408 + off) = lo4;
        return den_l;
    };

    const int rA = (lane & 7) + ((lane & 8) ? 8 : 0);
    const int cA = (lane & 16) ? 16 : 0;
    const int rB = (lane & 7) + ((lane & 16) ? 8 : 0);
    const int cB = (lane & 8) ? 16 : 0;
    const int g = lane >> 2, tig = lane & 3;

    issue(0); issue(1);
    CP_WAIT1();
    __syncthreads();
    {
        float d0acc = convert3_part(0, 0) + convert3_part(0, 1);
        denp[grp * 64 + tl] = d0acc;
    }
    __syncthreads();
    if (tid < 64) {
        float s8 = 0.f;
#pragma unroll
        for (int gi = 0; gi < 8; gi++) s8 += denp[gi * 64 + tid];
        zs[tid] = 1.0f / (s8 + EPS);
    }

    for (int i = 0; i < iters; i++) {
        CP_WAIT0();
        __syncthreads();                       // sync A
        issue(i + 2);
        const u32 qbase = sb + K3_QB + (i & 1) * 34816;
        const bool cvt = (i + 1 < iters);
        const int stn = (i + 1) & 1;
        float den_acc = 0.f;

        float acc[2][2][4];
#pragma unroll
        for (int a0 = 0; a0 < 2; a0++)
#pragma unroll
            for (int a1 = 0; a1 < 2; a1++)
#pragma unroll
                for (int r = 0; r < 4; r++) acc[a0][a1][r] = 0.f;
#pragma unroll
        for (int kk = 0; kk < 8; kk++) {
            const u32 boff = (u32)((wt * 16 + rB) * P3 + kk * 32 + cB);
            u32 bh0, bh1, bh2, bh3, bl0, bl1, bl2, bl3;
            ldsm4(bh0, bh1, bh2, bh3, qbase + boff);
            ldsm4(bl0, bl1, bl2, bl3, qbase + 17408 + boff);
            u32 ah[2][4], al[2][4];
#pragma unroll
            for (int mt = 0; mt < 2; mt++) {
                const u32 aoff = (u32)((we * 32 + mt * 16 + rA) * P3 + kk * 32 + cA);
                ldsm4(ah[mt][0], ah[mt][1], ah[mt][2], ah[mt][3], sb + K3_AHI + aoff);
                ldsm4(al[mt][0], al[mt][1], al[mt][2], al[mt][3], sb + K3_ALO + aoff);
            }
            if (cvt && kk == 1) den_acc += convert3_part(stn, 0);
            if (cvt && kk == 5) den_acc += convert3_part(stn, 1);
#pragma unroll
            for (int mt = 0; mt < 2; mt++) {
                mma16816(acc[mt][0], ah[mt][0], ah[mt][1], ah[mt][2], ah[mt][3], bh0, bh1);
                mma16816(acc[mt][0], ah[mt][0], ah[mt][1], ah[mt][2], ah[mt][3], bl0, bl1);
                mma16816(acc[mt][0], al[mt][0], al[mt][1], al[mt][2], al[mt][3], bh0, bh1);
                mma16816(acc[mt][1], ah[mt][0], ah[mt][1], ah[mt][2], ah[mt][3], bh2, bh3);
                mma16816(acc[mt][1], ah[mt][0], ah[mt][1], ah[mt][2], ah[mt][3], bl2, bl3);
                mma16816(acc[mt][1], al[mt][0], al[mt][1], al[mt][2], al[mt][3], bh2, bh3);
            }
        }
        if (cvt) denp[stn * 512 + grp * 64 + tl] = den_acc;
        __syncthreads();                       // sync B
        if (cvt && tid < 64) {
            const int o = stn * 512;
            float s8 = 0.f;
#pragma unroll
            for (int gi = 0; gi < 8; gi++) s8 += denp[o + gi * 64 + tid];
            zs[stn * 64 + tid] = 1.0f / (s8 + EPS);
        }
        // ---- epilogue(i): scale by zs(i) + store out^T ----
        const int T0 = (beg + i) * 64;
        const int zb = (i & 1) * 64;
#pragma unroll
        for (int mt = 0; mt < 2; mt++)
#pragma unroll
            for (int nt = 0; nt < 2; nt++) {
                const int e0 = we * 32 + mt * 16 + g;
                const int lt = wt * 16 + nt * 8 + tig * 2;
                const float z0 = zs[zb + lt], z1 = zs[zb + lt + 1];
                float* c = acc[mt][nt];
                *(float2*)(ob + (size_t)e0 * NTOK + T0 + lt) =
                    make_float2(c[0] * z0, c[1] * z1);
                *(float2*)(ob + (size_t)(e0 + 8) * NTOK + T0 + lt) =
                    make_float2(c[2] * z0, c[3] * z1);
            }
    }
}

// ====================================================================
extern "C" void kernel_launch(void* const* d_in, const int* in_sizes, int n_in,
                              void* d_out, int out_size) {
    const float* q = (const float*)d_in[0];
    const float* k = (const float*)d_in[1];
    const float* v = (const float*)d_in[2];
    float* out = (float*)d_out;

    cudaFuncSetAttribute(k1_mma, cudaFuncAttributeMaxDynamicSharedMemorySize, K1_SMEM);
    cudaFuncSetAttribute(k3_mma, cudaFuncAttributeMaxDynamicSharedMemorySize, K3_SMEM);

    k1_mma<<<dim3(SPLIT, BATCH), 512, K1_SMEM>>>(k, v);
    k2_reduce<<<(BATCH * DIM * DIM + 255) / 256, 256>>>();
    k3_mma<<<dim3(SPLIT, BATCH), 512, K3_SMEM>>>(q, out);
}

// round 16
// speedup vs baseline: 1.0447x; 1.0447x over previous
#include <cuda_runtime.h>
#include <cuda_bf16.h>
#include <cstdint>

#define BATCH 8
#define DIM   128
#define NTOK  32768
#define SPLIT 18               // 144 CTAs on 148 SMs
#define NST1  1024             // total 32-token stages per batch (k1)
#define NST3  512              // total 64-token stages per batch (k3)
#define EPS 1e-8f

typedef uint32_t u32;
typedef uint64_t u64;

// ---------------- scratch ----------------
__device__ __align__(16) float g_KVp[BATCH][SPLIT][DIM * DIM];
__device__ __align__(16) float g_Ksump[BATCH][SPLIT][DIM];
__device__ __align__(16) __nv_bfloat16 g_KVThi[BATCH][DIM * DIM]; // KV^T (row e, col d)
__device__ __align__(16) __nv_bfloat16 g_KVTlo[BATCH][DIM * DIM];
__device__ __align__(16) float g_Ksum[BATCH][DIM];

// ---------------- helpers ----------------
__device__ __forceinline__ u32 smem_u32(const void* p) {
    u32 a;
    asm("{ .reg .u64 t; cvta.to.shared.u64 t, %1; cvt.u32.u64 %0, t; }" : "=r"(a) : "l"(p));
    return a;
}
__device__ __forceinline__ void ldsm4(u32& r0, u32& r1, u32& r2, u32& r3, u32 addr) {
    asm volatile("ldmatrix.sync.aligned.m8n8.x4.shared.b16 {%0,%1,%2,%3}, [%4];"
                 : "=r"(r0), "=r"(r1), "=r"(r2), "=r"(r3) : "r"(addr));
}
// NON-volatile: lets ptxas interleave convert ALU work with the HMMA stream.
__device__ __forceinline__ void mma16816(float* c, u32 a0, u32 a1, u32 a2, u32 a3,
                                         u32 b0, u32 b1) {
    asm("mma.sync.aligned.m16n8k16.row.col.f32.bf16.bf16.f32 "
        "{%0,%1,%2,%3}, {%4,%5,%6,%7}, {%8,%9}, {%0,%1,%2,%3};"
        : "+f"(c[0]), "+f"(c[1]), "+f"(c[2]), "+f"(c[3])
        : "r"(a0), "r"(a1), "r"(a2), "r"(a3), "r"(b0), "r"(b1));
}
__device__ __forceinline__ void cpa16(u32 dst, const void* src) {
    asm volatile("cp.async.cg.shared.global [%0], [%1], 16;" :: "r"(dst), "l"(src));
}
#define CP_COMMIT() asm volatile("cp.async.commit_group;" ::: "memory")
#define CP_WAIT0()  asm volatile("cp.async.wait_group 0;" ::: "memory")
#define CP_WAIT1()  asm volatile("cp.async.wait_group 1;" ::: "memory")

__device__ __forceinline__ float phi(float x) { return x > 0.0f ? x + 1.0f : __expf(x); }

// truncation split: hi = top-16-bits of a,b packed; lo = bf16-rounded remainders
__device__ __forceinline__ void split2c(float a, float b, u32& hi, u32& lo) {
    u32 ab = __float_as_uint(a), bb = __float_as_uint(b);
    hi = __byte_perm(ab, bb, 0x7632);
    float la = a - __uint_as_float(ab & 0xffff0000u);
    float lb = b - __uint_as_float(bb & 0xffff0000u);
    asm("cvt.rn.bf16x2.f32 %0, %1, %2;" : "=r"(lo) : "f"(lb), "f"(la));
}

// ====================================================================
// k1: KV[d][e] = sum_n phi(K[d,n]) * V[e,n]
// 512 thr (16 warps), ~57 stages of 32 tokens, warp tile 32d x 32e.
// kk-section software-pipelined: B ldsm -> A0 ldsm -> MMA0 -> A1 ldsm
// -> convert slice -> MMA1.
// ====================================================================
#define P1 80
#define TB1 10240
#define STG1 40960
#define K1_RAW 81920
#define K1_KSB 147456
#define K1_SMEM 151552

__global__ __launch_bounds__(512, 1)
void k1_mma(const float* __restrict__ k, const float* __restrict__ v) {
    extern __shared__ __align__(16) char sm[];
    const u32 sb = smem_u32(sm);
    const int b = blockIdx.y, s = blockIdx.x;
    const int tid = threadIdx.x, wid = tid >> 5, lane = tid & 31;
    const int n4 = tid & 7, dr = tid >> 3;
    const int wd = wid >> 2, we = wid & 3;

    const int beg   = (s * NST1) / SPLIT;
    const int iters = ((s + 1) * NST1) / SPLIT - beg;

    const float* kb = k + (size_t)b * DIM * NTOK;
    const float* vb = v + (size_t)b * DIM * NTOK;

    const int rA = (lane & 7) + ((lane & 8) ? 8 : 0);
    const int cA = (lane & 16) ? 16 : 0;
    const int rB = (lane & 7) + ((lane & 16) ? 8 : 0);
    const int cB = (lane & 8) ? 16 : 0;

    float acc[2][4][4];
#pragma unroll
    for (int i = 0; i < 2; i++)
#pragma unroll
        for (int j = 0; j < 4; j++)
#pragma unroll
            for (int r = 0; r < 4; r++) acc[i][j][r] = 0.f;
    float ksum_l[2] = {0.f, 0.f};

    auto issue = [&](int tile) {
        if (tile >= iters) return;
        const int n0 = (beg + tile) * 32;
        const u32 rb = sb + K1_RAW + (tile & 1) * 32768;
#pragma unroll
        for (int c = 0; c < 2; c++) {
            const int ci = tid + c * 512;
            const int d = ci >> 3, col = ci & 7;
            cpa16(rb + d * 128 + col * 16, kb + (size_t)d * NTOK + n0 + col * 4);
            cpa16(rb + 16384 + d * 128 + col * 16, vb + (size_t)d * NTOK + n0 + col * 4);
        }
        CP_COMMIT();
    };

    auto convert_part = [&](int st, int part) {
        char* stp = sm + st * STG1;
        const char* rp = sm + K1_RAW + st * 32768;
        const int d = part * 64 + dr;
        const u32 roff = (u32)(d * 128 + n4 * 16);
        const u32 off  = (u32)(d * P1 + n4 * 8);
        float4 kx = *(const float4*)(rp + roff);
        float f0 = phi(kx.x), f1 = phi(kx.y), f2 = phi(kx.z), f3 = phi(kx.w);
        ksum_l[part] += (f0 + f1) + (f2 + f3);
        uint2 hi, lo;
        split2c(f0, f1, hi.x, lo.x);
        split2c(f2, f3, hi.y, lo.y);
        *(uint2*)(stp + 0       + off) = hi;
        *(uint2*)(stp + TB1     + off) = lo;
        float4 vx = *(const float4*)(rp + 16384 + roff);
        split2c(vx.x, vx.y, hi.x, lo.x);
        split2c(vx.z, vx.w, hi.y, lo.y);
        *(uint2*)(stp + 2 * TB1 + off) = hi;
        *(uint2*)(stp + 3 * TB1 + off) = lo;
    };

    issue(0); issue(1);
    CP_WAIT1();
    __syncthreads();
    convert_part(0, 0); convert_part(0, 1);

    for (int i = 0; i < iters; i++) {
        CP_WAIT0();
        __syncthreads();
        issue(i + 2);
        const u32 base = sb + (i & 1) * STG1;
        const bool cvt = (i + 1 < iters);
        const int stn = (i + 1) & 1;
#pragma unroll
        for (int kk = 0; kk < 2; kk++) {
            // ---- B fragments ----
            u32 bh[8], bl[8];
#pragma unroll
            for (int g = 0; g < 2; g++) {
                const u32 boff = (u32)((we * 32 + g * 16 + rB) * P1 + kk * 32 + cB);
                ldsm4(bh[g*4+0], bh[g*4+1], bh[g*4+2], bh[g*4+3], base + 2 * TB1 + boff);
                ldsm4(bl[g*4+0], bl[g*4+1], bl[g*4+2], bl[g*4+3], base + 3 * TB1 + boff);
            }
            // ---- A fragments mt=0 ----
            u32 ah0[4], al0[4];
            {
                const u32 aoff = (u32)((wd * 32 + rA) * P1 + kk * 32 + cA);
                ldsm4(ah0[0], ah0[1], ah0[2], ah0[3], base + 0   + aoff);
                ldsm4(al0[0], al0[1], al0[2], al0[3], base + TB1 + aoff);
            }
            // ---- MMA mt=0 (tensor starts while A1 loads below) ----
#pragma unroll
            for (int nt = 0; nt < 4; nt++) {
                float* c = acc[0][nt];
                const int bi = (nt >> 1) * 4 + (nt & 1) * 2;
                mma16816(c, ah0[0], ah0[1], ah0[2], ah0[3], bh[bi], bh[bi+1]);
                mma16816(c, ah0[0], ah0[1], ah0[2], ah0[3], bl[bi], bl[bi+1]);
                mma16816(c, al0[0], al0[1], al0[2], al0[3], bh[bi], bh[bi+1]);
            }
            // ---- A fragments mt=1 ----
            u32 ah1[4], al1[4];
            {
                const u32 aoff = (u32)((wd * 32 + 16 + rA) * P1 + kk * 32 + cA);
                ldsm4(ah1[0], ah1[1], ah1[2], ah1[3], base + 0   + aoff);
                ldsm4(al1[0], al1[1], al1[2], al1[3], base + TB1 + aoff);
            }
            // ---- convert slice for stage i+1 (covers A1 scoreboard) ----
            if (cvt) convert_part(stn, kk);
            // ---- MMA mt=1 ----
#pragma unroll
            for (int nt = 0; nt < 4; nt++) {
                float* c = acc[1][nt];
                const int bi = (nt >> 1) * 4 + (nt & 1) * 2;
                mma16816(c, ah1[0], ah1[1], ah1[2], ah1[3], bh[bi], bh[bi+1]);
                mma16816(c, ah1[0], ah1[1], ah1[2], ah1[3], bl[bi], bl[bi+1]);
                mma16816(c, al1[0], al1[1], al1[2], al1[3], bh[bi], bh[bi+1]);
            }
        }
    }
    __syncthreads();
    float* kbuf = (float*)(sm + K1_KSB);
#pragma unroll
    for (int p = 0; p < 2; p++) kbuf[(p * 64 + dr) * 8 + n4] = ksum_l[p];
    __syncthreads();
    if (tid < 128) {
        float sum = 0.f;
#pragma unroll
        for (int i = 0; i < 8; i++) sum += kbuf[tid * 8 + i];
        g_Ksump[b][s][tid] = sum;
    }
    float* dst = &g_KVp[b][s][0];
    const int g = lane >> 2, tig = lane & 3;
#pragma unroll
    for (int mt = 0; mt < 2; mt++)
#pragma unroll
        for (int nt = 0; nt < 4; nt++) {
            const int d0 = wd * 32 + mt * 16 + g;
            const int e0 = we * 32 + nt * 8 + tig * 2;
            float* c = acc[mt][nt];
            *(float2*)(dst + d0 * DIM + e0)       = make_float2(c[0], c[1]);
            *(float2*)(dst + (d0 + 8) * DIM + e0) = make_float2(c[2], c[3]);
        }
}

// ====================================================================
// k2: reduce partials -> KV^T bf16 hi/lo + Ksum fp32   (UNCHANGED)
// ====================================================================
__global__ __launch_bounds__(256)
void k2_reduce() {
    const int idx = blockIdx.x * 256 + threadIdx.x;
    if (idx < BATCH * DIM * DIM) {
        const int b = idx >> 14, e = idx & 127, d = (idx >> 7) & 127;
        float sum = 0.f;
#pragma unroll
        for (int p = 0; p < SPLIT; p++) sum += g_KVp[b][p][d * DIM + e];
        __nv_bfloat16 h = __float2bfloat16(sum);
        g_KVThi[b][e * DIM + d] = h;
        g_KVTlo[b][e * DIM + d] = __float2bfloat16(sum - __bfloat162float(h));
    }
    if (idx < BATCH * DIM) {
        const int b = idx >> 7, d = idx & 127;
        float sum = 0.f;
#pragma unroll
        for (int p = 0; p < SPLIT; p++) sum += g_Ksump[b][p][d];
        g_Ksum[b][d] = sum;
    }
}

// ====================================================================
// k3: out^T[e][t] = z(t) * sum_d KV^T[e,d] * phi(Q[t,d])
// 256 thr (R14 shape), ~29 stages of 64 tokens, warp tile 32e x 32t.
// kk-section software-pipelined like k1.
// ====================================================================
#define P3 272
#define K3_AHI 0
#define K3_ALO 34816
#define K3_QB  69632          // stage st: QHI +st*34816, QLO +17408
#define K3_RAW 139264         // + st*32768: [128 d][64 t] f32, pitch 256B
#define K3_ZS  204800         // 2 x 64 f32
#define K3_KS  205312         // 128 f32
#define K3_DEN 205824         // 2 x 4 x 64 f32
#define K3_SMEM 208896

__global__ __launch_bounds__(256, 1)
void k3_mma(const float* __restrict__ q, float* __restrict__ out) {
    extern __shared__ __align__(16) char sm[];
    const u32 sb = smem_u32(sm);
    const int b = blockIdx.y, s = blockIdx.x;
    const int tid = threadIdx.x, wid = tid >> 5, lane = tid & 31;
    const int we = wid >> 1, wt = wid & 1;      // 32e x 32t warp tile
    const int dg = we;                          // convert d-group (0..3)
    const int tl = wt * 32 + lane;              // convert token (0..63)

    const int beg   = (s * NST3) / SPLIT;
    const int iters = ((s + 1) * NST3) / SPLIT - beg;

    // resident KV^T hi/lo
    for (int i = tid; i < DIM * 64; i += 256) {
        const int e = i >> 6, dp = i & 63;
        const u32 off = (u32)(e * P3 + dp * 4);
        *(u32*)(sm + K3_AHI + off) = *(const u32*)(&g_KVThi[b][e * DIM + dp * 2]);
        *(u32*)(sm + K3_ALO + off) = *(const u32*)(&g_KVTlo[b][e * DIM + dp * 2]);
    }
    float* zs = (float*)(sm + K3_ZS);
    float* ks = (float*)(sm + K3_KS);
    float* denp = (float*)(sm + K3_DEN);
    if (tid < 128) ks[tid] = g_Ksum[b][tid];

    const float* qb = q + (size_t)b * DIM * NTOK;
    float* ob = out + (size_t)b * DIM * NTOK;

    auto issue = [&](int tile) {
        if (tile >= iters) return;
        const int T0 = (beg + tile) * 64;
        const u32 rb = sb + K3_RAW + (tile & 1) * 32768;
#pragma unroll
        for (int c = 0; c < 8; c++) {
            const int ci = tid + c * 256;         // 0..2047
            const int d = ci >> 4, col = ci & 15;
            cpa16(rb + d * 256 + col * 16, qb + (size_t)d * NTOK + T0 + col * 4);
        }
        CP_COMMIT();
    };

    // convert 4 d-pairs (part p in 0..3) of stage st; returns den partial
    auto convert3_part = [&](int st, int p) -> float {
        const char* rp = sm + K3_RAW + st * 32768;
        char* qsm = sm + K3_QB + st * 34816;
        uint4 hi4, lo4;
        u32* hp = (u32*)&hi4; u32* lp = (u32*)&lo4;
        float den_l = 0.f;
#pragma unroll
        for (int jj = 0; jj < 4; jj++) {
            const int dp = dg * 16 + p * 4 + jj, d0 = dp * 2;
            float f0 = phi(*(const float*)(rp + d0 * 256 + tl * 4));
            float f1 = phi(*(const float*)(rp + (d0 + 1) * 256 + tl * 4));
            split2c(f0, f1, hp[jj], lp[jj]);
            den_l += f0 * ks[d0] + f1 * ks[d0 + 1];
        }
        const u32 off = (u32)(tl * P3 + (dg * 16 + p * 4) * 4);
        *(uint4*)(qsm + off)         = hi4;
        *(uint4*)(qsm + 17408 + off) = lo4;
        return den_l;
    };

    const int rA = (lane & 7) + ((lane & 8) ? 8 : 0);
    const int cA = (lane & 16) ? 16 : 0;
    const int rB = (lane & 7) + ((lane & 16) ? 8 : 0);
    const int cB = (lane & 8) ? 16 : 0;
    const int g = lane >> 2, tig = lane & 3;

    issue(0); issue(1);
    CP_WAIT1();
    __syncthreads();
    {
        float d0acc = convert3_part(0, 0) + convert3_part(0, 1)
                    + convert3_part(0, 2) + convert3_part(0, 3);
        denp[dg * 64 + tl] = d0acc;
    }
    __syncthreads();
    if (tid < 64)
        zs[tid] = 1.0f / (denp[tid] + denp[64 + tid] + denp[128 + tid] + denp[192 + tid] + EPS);

    for (int i = 0; i < iters; i++) {
        CP_WAIT0();
        __syncthreads();                       // sync A
        issue(i + 2);
        const u32 qbase = sb + K3_QB + (i & 1) * 34816;
        const bool cvt = (i + 1 < iters);
        const int stn = (i + 1) & 1;
        float den_acc = 0.f;

        float acc[2][4][4];
#pragma unroll
        for (int a0 = 0; a0 < 2; a0++)
#pragma unroll
            for (int a1 = 0; a1 < 4; a1++)
#pragma unroll
                for (int r = 0; r < 4; r++) acc[a0][a1][r] = 0.f;
#pragma unroll
        for (int kk = 0; kk < 8; kk++) {
            // ---- B fragments ----
            u32 bh[8], bl[8];
#pragma unroll
            for (int gg = 0; gg < 2; gg++) {
                const u32 boff = (u32)((wt * 32 + gg * 16 + rB) * P3 + kk * 32 + cB);
                ldsm4(bh[gg*4+0], bh[gg*4+1], bh[gg*4+2], bh[gg*4+3], qbase + boff);
                ldsm4(bl[gg*4+0], bl[gg*4+1], bl[gg*4+2], bl[gg*4+3], qbase + 17408 + boff);
            }
            // ---- A fragments mt=0 ----
            u32 ah0[4], al0[4];
            {
                const u32 aoff = (u32)((we * 32 + rA) * P3 + kk * 32 + cA);
                ldsm4(ah0[0], ah0[1], ah0[2], ah0[3], sb + K3_AHI + aoff);
                ldsm4(al0[0], al0[1], al0[2], al0[3], sb + K3_ALO + aoff);
            }
            // ---- MMA mt=0 ----
#pragma unroll
            for (int nt = 0; nt < 4; nt++) {
                float* c = acc[0][nt];
                const int bi = (nt >> 1) * 4 + (nt & 1) * 2;
                mma16816(c, ah0[0], ah0[1], ah0[2], ah0[3], bh[bi], bh[bi+1]);
                mma16816(c, ah0[0], ah0[1], ah0[2], ah0[3], bl[bi], bl[bi+1]);
                mma16816(c, al0[0], al0[1], al0[2], al0[3], bh[bi], bh[bi+1]);
            }
            // ---- A fragments mt=1 ----
            u32 ah1[4], al1[4];
            {
                const u32 aoff = (u32)((we * 32 + 16 + rA) * P3 + kk * 32 + cA);
                ldsm4(ah1[0], ah1[1], ah1[2], ah1[3], sb + K3_AHI + aoff);
                ldsm4(al1[0], al1[1], al1[2], al1[3], sb + K3_ALO + aoff);
            }
            // ---- convert slice (odd kk) covers A1 scoreboard ----
            if (cvt && (kk & 1)) den_acc += convert3_part(stn, kk >> 1);
            // ---- MMA mt=1 ----
#pragma unroll
            for (int nt = 0; nt < 4; nt++) {
                float* c = acc[1][nt];
                const int bi = (nt >> 1) * 4 + (nt & 1) * 2;
                mma16816(c, ah1[0], ah1[1], ah1[2], ah1[3], bh[bi], bh[bi+1]);
                mma16816(c, ah1[0], ah1[1], ah1[2], ah1[3], bl[bi], bl[bi+1]);
                mma16816(c, al1[0], al1[1], al1[2], al1[3], bh[bi], bh[bi+1]);
            }
        }
        if (cvt) denp[stn * 256 + dg * 64 + tl] = den_acc;
        __syncthreads();                       // sync B
        if (cvt && tid < 64) {
            const int o = stn * 256;
            zs[stn * 64 + tid] = 1.0f / (denp[o + tid] + denp[o + 64 + tid]
                                       + denp[o + 128 + tid] + denp[o + 192 + tid] + EPS);
        }
        // ---- epilogue(i): scale by zs(i) + store out^T ----
        const int T0 = (beg + i) * 64;
        const int zb = (i & 1) * 64;
#pragma unroll
        for (int mt = 0; mt < 2; mt++)
#pragma unroll
            for (int nt = 0; nt < 4; nt++) {
                const int e0 = we * 32 + mt * 16 + g;
                const int lt = wt * 32 + nt * 8 + tig * 2;
                const float z0 = zs[zb + lt], z1 = zs[zb + lt + 1];
                float* c = acc[mt][nt];
                *(float2*)(ob + (size_t)e0 * NTOK + T0 + lt) =
                    make_float2(c[0] * z0, c[1] * z1);
                *(float2*)(ob + (size_t)(e0 + 8) * NTOK + T0 + lt) =
                    make_float2(c[2] * z0, c[3] * z1);
            }
    }
}

// ====================================================================
extern "C" void kernel_launch(void* const* d_in, const int* in_sizes, int n_in,
                              void* d_out, int out_size) {
    const float* q = (const float*)d_in[0];
    const float* k = (const float*)d_in[1];
    const float* v = (const float*)d_in[2];
    float* out = (float*)d_out;

    cudaFuncSetAttribute(k1_mma, cudaFuncAttributeMaxDynamicSharedMemorySize, K1_SMEM);
    cudaFuncSetAttribute(k3_mma, cudaFuncAttributeMaxDynamicSharedMemorySize, K3_SMEM);

    k1_mma<<<dim3(SPLIT, BATCH), 512, K1_SMEM>>>(k, v);
    k2_reduce<<<(BATCH * DIM * DIM + 255) / 256, 256>>>();
    k3_mma<<<dim3(SPLIT, BATCH), 256, K3_SMEM>>>(q, out);
}